// round 1
// baseline (speedup 1.0000x reference)
#include <cuda_runtime.h>
#include <cuda_bf16.h>
#include <math.h>

// Problem constants
#define BATCH 2
#define SEQ   2048
#define DM    1024
#define HEADS 16
#define DK    64
#define MROWS (BATCH*SEQ)   // 4096
#define INV_SCALE 0.125f    // 1/sqrt(64)

// Scratch (static device memory; allocation APIs are forbidden)
__device__ float g_q[BATCH*HEADS*SEQ*DK];    // [b*H+h][s][dk]
__device__ float g_k[BATCH*HEADS*SEQ*DK];
__device__ float g_v[BATCH*HEADS*SEQ*DK];
__device__ float g_ctx[MROWS*DM];            // [b*S+s][h*64+d]

// ---------------------------------------------------------------------------
// GEMM: C[m,n] = sum_k X[m,k]*W[n,k] + bias[n]
// X: [4096,1024] row-major, W: [1024,1024] row-major (torch Linear weight)
// Tile: 128x128x8, 256 threads, 8x8 per-thread micro-tile.
// MODE 0: epilogue writes head-split QKV layout into g_q/g_k/g_v (z selects)
// MODE 1: epilogue writes plain [m*1024+n] to Out
// ---------------------------------------------------------------------------

__global__ void __launch_bounds__(256)
qkv_gemm_kernel(const float* __restrict__ Xq, const float* __restrict__ Xk,
                const float* __restrict__ Xv,
                const float* __restrict__ Wq, const float* __restrict__ Wk,
                const float* __restrict__ Wv,
                const float* __restrict__ Bq, const float* __restrict__ Bk,
                const float* __restrict__ Bv)
{
    __shared__ float As[8][132];
    __shared__ float Bs[8][132];

    const int z = blockIdx.z;
    const float* __restrict__ X  = (z == 0) ? Xq : (z == 1) ? Xk : Xv;
    const float* __restrict__ W  = (z == 0) ? Wq : (z == 1) ? Wk : Wv;
    const float* __restrict__ Bi = (z == 0) ? Bq : (z == 1) ? Bk : Bv;
    float* __restrict__ Out      = (z == 0) ? g_q : (z == 1) ? g_k : g_v;

    const int m0 = blockIdx.y * 128;
    const int n0 = blockIdx.x * 128;
    const int tid = threadIdx.x;
    const int lrow = tid >> 1;          // 0..127
    const int lk   = (tid & 1) * 4;     // 0 or 4
    const int ty = tid >> 4;            // 0..15
    const int tx = tid & 15;            // 0..15

    float acc[8][8];
#pragma unroll
    for (int i = 0; i < 8; i++)
#pragma unroll
        for (int j = 0; j < 8; j++) acc[i][j] = 0.f;

    for (int kt = 0; kt < DM; kt += 8) {
        float4 av = *(const float4*)&X[(m0 + lrow) * DM + kt + lk];
        float4 bv = *(const float4*)&W[(n0 + lrow) * DM + kt + lk];
        As[lk + 0][lrow] = av.x; As[lk + 1][lrow] = av.y;
        As[lk + 2][lrow] = av.z; As[lk + 3][lrow] = av.w;
        Bs[lk + 0][lrow] = bv.x; Bs[lk + 1][lrow] = bv.y;
        Bs[lk + 2][lrow] = bv.z; Bs[lk + 3][lrow] = bv.w;
        __syncthreads();

#pragma unroll
        for (int k = 0; k < 8; k++) {
            float4 a0 = *(const float4*)&As[k][ty * 8];
            float4 a1 = *(const float4*)&As[k][ty * 8 + 4];
            float4 b0 = *(const float4*)&Bs[k][tx * 8];
            float4 b1 = *(const float4*)&Bs[k][tx * 8 + 4];
            float a[8] = {a0.x, a0.y, a0.z, a0.w, a1.x, a1.y, a1.z, a1.w};
            float b[8] = {b0.x, b0.y, b0.z, b0.w, b1.x, b1.y, b1.z, b1.w};
#pragma unroll
            for (int i = 0; i < 8; i++)
#pragma unroll
                for (int j = 0; j < 8; j++) acc[i][j] = fmaf(a[i], b[j], acc[i][j]);
        }
        __syncthreads();
    }

    // Epilogue: head-split layout [b*H+h][s][d]
#pragma unroll
    for (int i = 0; i < 8; i++) {
        const int m = m0 + ty * 8 + i;
        const int bb = m >> 11;          // m / 2048
        const int s  = m & 2047;
#pragma unroll
        for (int j = 0; j < 8; j++) {
            const int n = n0 + tx * 8 + j;
            const int h = n >> 6;
            const int d = n & 63;
            Out[(((bb * HEADS + h) * SEQ) + s) * DK + d] = acc[i][j] + Bi[n];
        }
    }
}

__global__ void __launch_bounds__(256)
oproj_gemm_kernel(const float* __restrict__ W, const float* __restrict__ Bi,
                  float* __restrict__ Out)
{
    __shared__ float As[8][132];
    __shared__ float Bs[8][132];

    const float* __restrict__ X = g_ctx;
    const int m0 = blockIdx.y * 128;
    const int n0 = blockIdx.x * 128;
    const int tid = threadIdx.x;
    const int lrow = tid >> 1;
    const int lk   = (tid & 1) * 4;
    const int ty = tid >> 4;
    const int tx = tid & 15;

    float acc[8][8];
#pragma unroll
    for (int i = 0; i < 8; i++)
#pragma unroll
        for (int j = 0; j < 8; j++) acc[i][j] = 0.f;

    for (int kt = 0; kt < DM; kt += 8) {
        float4 av = *(const float4*)&X[(m0 + lrow) * DM + kt + lk];
        float4 bv = *(const float4*)&W[(n0 + lrow) * DM + kt + lk];
        As[lk + 0][lrow] = av.x; As[lk + 1][lrow] = av.y;
        As[lk + 2][lrow] = av.z; As[lk + 3][lrow] = av.w;
        Bs[lk + 0][lrow] = bv.x; Bs[lk + 1][lrow] = bv.y;
        Bs[lk + 2][lrow] = bv.z; Bs[lk + 3][lrow] = bv.w;
        __syncthreads();

#pragma unroll
        for (int k = 0; k < 8; k++) {
            float4 a0 = *(const float4*)&As[k][ty * 8];
            float4 a1 = *(const float4*)&As[k][ty * 8 + 4];
            float4 b0 = *(const float4*)&Bs[k][tx * 8];
            float4 b1 = *(const float4*)&Bs[k][tx * 8 + 4];
            float a[8] = {a0.x, a0.y, a0.z, a0.w, a1.x, a1.y, a1.z, a1.w};
            float b[8] = {b0.x, b0.y, b0.z, b0.w, b1.x, b1.y, b1.z, b1.w};
#pragma unroll
            for (int i = 0; i < 8; i++)
#pragma unroll
                for (int j = 0; j < 8; j++) acc[i][j] = fmaf(a[i], b[j], acc[i][j]);
        }
        __syncthreads();
    }

#pragma unroll
    for (int i = 0; i < 8; i++) {
        const int m = m0 + ty * 8 + i;
#pragma unroll
        for (int j = 0; j < 8; j++) {
            const int n = n0 + tx * 8 + j;
            Out[m * DM + n] = acc[i][j] + Bi[n];
        }
    }
}

// ---------------------------------------------------------------------------
// Flash attention (fp32, online softmax).
// grid: (SEQ/64, BATCH*HEADS), 256 threads (16x16), each thread 4x4 tile.
// Dynamic smem: Qs[64][65] k-major, Ks[64][65] k-major, Vs[64][68], Ps[64][68]
// ---------------------------------------------------------------------------
#define ATTN_SMEM_FLOATS (64*65 + 64*65 + 64*68 + 64*68)

__global__ void __launch_bounds__(256)
attn_kernel()
{
    extern __shared__ float sm[];
    float* Qs = sm;                    // [d][r], pitch 65
    float* Ks = Qs + 64 * 65;          // [d][c], pitch 65
    float* Vs = Ks + 64 * 65;          // [j][c], pitch 68
    float* Ps = Vs + 64 * 68;          // [r][c], pitch 68

    const int tid = threadIdx.x;
    const int ty = tid >> 4, tx = tid & 15;
    const int r0 = ty * 4, c0 = tx * 4;

    const int bh = blockIdx.y;
    const int q0 = blockIdx.x * 64;
    const float* __restrict__ Qg = g_q + (size_t)bh * SEQ * DK;
    const float* __restrict__ Kg = g_k + (size_t)bh * SEQ * DK;
    const float* __restrict__ Vg = g_v + (size_t)bh * SEQ * DK;

    // Load Q tile (scaled by 1/sqrt(dk)), k-major
    for (int t = tid; t < 64 * 16; t += 256) {
        const int row = t >> 4;
        const int dq = (t & 15) * 4;
        float4 v = *(const float4*)&Qg[(q0 + row) * DK + dq];
        Qs[(dq + 0) * 65 + row] = v.x * INV_SCALE;
        Qs[(dq + 1) * 65 + row] = v.y * INV_SCALE;
        Qs[(dq + 2) * 65 + row] = v.z * INV_SCALE;
        Qs[(dq + 3) * 65 + row] = v.w * INV_SCALE;
    }

    float m_run[4], l_run[4], o[4][4];
#pragma unroll
    for (int i = 0; i < 4; i++) {
        m_run[i] = -1e30f; l_run[i] = 0.f;
#pragma unroll
        for (int j = 0; j < 4; j++) o[i][j] = 0.f;
    }

    for (int kv0 = 0; kv0 < SEQ; kv0 += 64) {
        __syncthreads();  // protect Ks/Vs/Ps from previous consumers
        // Load K (k-major) and V (row-major) tiles
        for (int t = tid; t < 64 * 16; t += 256) {
            const int row = t >> 4;
            const int dq = (t & 15) * 4;
            float4 kv = *(const float4*)&Kg[(kv0 + row) * DK + dq];
            Ks[(dq + 0) * 65 + row] = kv.x;
            Ks[(dq + 1) * 65 + row] = kv.y;
            Ks[(dq + 2) * 65 + row] = kv.z;
            Ks[(dq + 3) * 65 + row] = kv.w;
            float4 vv = *(const float4*)&Vg[(kv0 + row) * DK + dq];
            *(float4*)&Vs[row * 68 + dq] = vv;
        }
        __syncthreads();

        // S = Q * K^T (scaled): each thread 4x4
        float s[4][4];
#pragma unroll
        for (int i = 0; i < 4; i++)
#pragma unroll
            for (int j = 0; j < 4; j++) s[i][j] = 0.f;

#pragma unroll 8
        for (int k = 0; k < 64; k++) {
            float a[4], b[4];
#pragma unroll
            for (int i = 0; i < 4; i++) a[i] = Qs[k * 65 + r0 + i];
#pragma unroll
            for (int j = 0; j < 4; j++) b[j] = Ks[k * 65 + c0 + j];
#pragma unroll
            for (int i = 0; i < 4; i++)
#pragma unroll
                for (int j = 0; j < 4; j++) s[i][j] = fmaf(a[i], b[j], s[i][j]);
        }

        // Row max over 64 cols: local max then shfl across the 16 tx lanes
        float mt[4];
#pragma unroll
        for (int i = 0; i < 4; i++) {
            mt[i] = fmaxf(fmaxf(s[i][0], s[i][1]), fmaxf(s[i][2], s[i][3]));
        }
#pragma unroll
        for (int off = 8; off >= 1; off >>= 1) {
#pragma unroll
            for (int i = 0; i < 4; i++)
                mt[i] = fmaxf(mt[i], __shfl_xor_sync(0xffffffffu, mt[i], off));
        }

        float mn[4], corr[4], rs[4];
#pragma unroll
        for (int i = 0; i < 4; i++) {
            mn[i] = fmaxf(m_run[i], mt[i]);
            corr[i] = __expf(m_run[i] - mn[i]);
            rs[i] = 0.f;
        }

        // P = exp(S - mn); write Ps; accumulate row sums
#pragma unroll
        for (int i = 0; i < 4; i++) {
            float p0 = __expf(s[i][0] - mn[i]);
            float p1 = __expf(s[i][1] - mn[i]);
            float p2 = __expf(s[i][2] - mn[i]);
            float p3 = __expf(s[i][3] - mn[i]);
            rs[i] = p0 + p1 + p2 + p3;
            *(float4*)&Ps[(r0 + i) * 68 + c0] = make_float4(p0, p1, p2, p3);
        }
#pragma unroll
        for (int off = 8; off >= 1; off >>= 1) {
#pragma unroll
            for (int i = 0; i < 4; i++)
                rs[i] += __shfl_xor_sync(0xffffffffu, rs[i], off);
        }
#pragma unroll
        for (int i = 0; i < 4; i++) {
            l_run[i] = l_run[i] * corr[i] + rs[i];
            m_run[i] = mn[i];
#pragma unroll
            for (int j = 0; j < 4; j++) o[i][j] *= corr[i];
        }
        __syncthreads();

        // O += P * V
#pragma unroll 8
        for (int j = 0; j < 64; j++) {
            float4 vv = *(const float4*)&Vs[j * 68 + c0];
            float pv[4];
#pragma unroll
            for (int i = 0; i < 4; i++) pv[i] = Ps[(r0 + i) * 68 + j];
#pragma unroll
            for (int i = 0; i < 4; i++) {
                o[i][0] = fmaf(pv[i], vv.x, o[i][0]);
                o[i][1] = fmaf(pv[i], vv.y, o[i][1]);
                o[i][2] = fmaf(pv[i], vv.z, o[i][2]);
                o[i][3] = fmaf(pv[i], vv.w, o[i][3]);
            }
        }
    }

    // Epilogue: ctx[b][s][h*64+d]
    const int b = bh >> 4;
    const int h = bh & 15;
#pragma unroll
    for (int i = 0; i < 4; i++) {
        const float inv = 1.0f / l_run[i];
        const int row = q0 + r0 + i;
        float* dst = &g_ctx[((size_t)(b * SEQ + row)) * DM + h * DK + c0];
        float4 w = make_float4(o[i][0] * inv, o[i][1] * inv, o[i][2] * inv, o[i][3] * inv);
        *(float4*)dst = w;
    }
}

// ---------------------------------------------------------------------------
extern "C" void kernel_launch(void* const* d_in, const int* in_sizes, int n_in,
                              void* d_out, int out_size)
{
    const float* query = (const float*)d_in[0];
    const float* key   = (const float*)d_in[1];
    const float* value = (const float*)d_in[2];
    const float* wq = (const float*)d_in[3];
    const float* bq = (const float*)d_in[4];
    const float* wk = (const float*)d_in[5];
    const float* bk = (const float*)d_in[6];
    const float* wv = (const float*)d_in[7];
    const float* bv = (const float*)d_in[8];
    const float* wo = (const float*)d_in[9];
    const float* bo = (const float*)d_in[10];
    float* out = (float*)d_out;

    // Opt-in to >48KB dynamic smem for the attention kernel (capture-safe).
    cudaFuncSetAttribute(attn_kernel, cudaFuncAttributeMaxDynamicSharedMemorySize,
                         ATTN_SMEM_FLOATS * (int)sizeof(float));

    // QKV projections: C[4096,1024] x3 fused via grid.z
    dim3 gq(DM / 128, MROWS / 128, 3);
    qkv_gemm_kernel<<<gq, 256>>>(query, key, value, wq, wk, wv, bq, bk, bv);

    // Flash attention
    dim3 ga(SEQ / 64, BATCH * HEADS);
    attn_kernel<<<ga, 256, ATTN_SMEM_FLOATS * (int)sizeof(float)>>>();

    // Output projection -> d_out
    dim3 go(DM / 128, MROWS / 128);
    oproj_gemm_kernel<<<go, 256>>>(wo, bo, out);
}

// round 12
// speedup vs baseline: 1.2389x; 1.2389x over previous
#include <cuda_runtime.h>
#include <cuda_bf16.h>
#include <math.h>
#include <stdint.h>

// Problem constants
#define BATCH 2
#define SEQ   2048
#define DM    1024
#define HEADS 16
#define DK    64
#define MROWS (BATCH*SEQ)   // 4096
#define INV_SCALE 0.125f

#define SZX (MROWS*DM)
#define SZW (DM*DM)

// ---------------- static device scratch ----------------
__device__ float g_q[BATCH*HEADS*SEQ*DK];
__device__ float g_k[BATCH*HEADS*SEQ*DK];
__device__ float g_v[BATCH*HEADS*SEQ*DK];
__device__ float g_ctx[MROWS*DM];

__device__ __align__(256) __nv_bfloat16 g_xh[3*SZX];
__device__ __align__(256) __nv_bfloat16 g_xl[3*SZX];
__device__ __align__(256) __nv_bfloat16 g_wh[4*SZW];
__device__ __align__(256) __nv_bfloat16 g_wl[4*SZW];
__device__ __align__(256) __nv_bfloat16 g_ch[SZX];
__device__ __align__(256) __nv_bfloat16 g_cl[SZX];

// ---------------- mma.sync helper (sm_80-era; valid on compute_103) --------
#define MMA16816(c, a, b) \
    asm volatile("mma.sync.aligned.m16n8k16.row.col.f32.bf16.bf16.f32 " \
        "{%0,%1,%2,%3}, {%4,%5,%6,%7}, {%8,%9}, {%0,%1,%2,%3};" \
        : "+f"((c)[0]), "+f"((c)[1]), "+f"((c)[2]), "+f"((c)[3]) \
        : "r"((a)[0]), "r"((a)[1]), "r"((a)[2]), "r"((a)[3]), \
          "r"((b)[0]), "r"((b)[1]))

// ---------------------------------------------------------------------------
// fp32 -> bf16 hi/lo split.
// CRITICAL FIX: destination resolved IN DEVICE CODE via selector. Passing
// __device__ symbol addresses from host code yields host-shadow addresses;
// on GB300 (ATS) the GPU happily writes host memory -> device arrays stay 0.
// which: 0/1/2 -> g_xh/g_xl slot (query/key/value)
//        3/4/5/6 -> g_wh/g_wl slot (wq/wk/wv/wo)
//        7 -> g_ch/g_cl, source = g_ctx (src arg ignored)
// ---------------------------------------------------------------------------
__global__ void __launch_bounds__(256)
cvt_kernel(const float* __restrict__ src, int which, int n4)
{
    int i = blockIdx.x * 256 + threadIdx.x;
    if (i >= n4) return;

    __nv_bfloat16* hi;
    __nv_bfloat16* lo;
    const float* s = src;
    if (which < 3)      { hi = g_xh + (size_t)which * SZX;       lo = g_xl + (size_t)which * SZX; }
    else if (which < 7) { hi = g_wh + (size_t)(which - 3) * SZW; lo = g_wl + (size_t)(which - 3) * SZW; }
    else                { hi = g_ch; lo = g_cl; s = g_ctx; }

    float4 v = ((const float4*)s)[i];
    __nv_bfloat16 h0 = __float2bfloat16(v.x);
    __nv_bfloat16 h1 = __float2bfloat16(v.y);
    __nv_bfloat16 h2 = __float2bfloat16(v.z);
    __nv_bfloat16 h3 = __float2bfloat16(v.w);
    __nv_bfloat16 l0 = __float2bfloat16(v.x - __bfloat162float(h0));
    __nv_bfloat16 l1 = __float2bfloat16(v.y - __bfloat162float(h1));
    __nv_bfloat16 l2 = __float2bfloat16(v.z - __bfloat162float(h2));
    __nv_bfloat16 l3 = __float2bfloat16(v.w - __bfloat162float(h3));
    __nv_bfloat162* H = (__nv_bfloat162*)hi;
    __nv_bfloat162* L = (__nv_bfloat162*)lo;
    H[2*i]   = __nv_bfloat162(h0, h1);
    H[2*i+1] = __nv_bfloat162(h2, h3);
    L[2*i]   = __nv_bfloat162(l0, l1);
    L[2*i+1] = __nv_bfloat162(l2, l3);
}

// ---------------------------------------------------------------------------
// mma.sync GEMM: C[m,n] = sum_k A[m,k]*B[n,k] + bias[n], 3-term bf16 split.
// Tile 128x128, 256 threads, warp grid 4(M) x 2(N), warp tile 32x64.
// All A/B matrices referenced via device globals INSIDE the kernel.
// mode 0: z selects q/k/v; head-split epilogue to g_q/g_k/g_v.
// mode 1: ctx @ wo^T -> out (plain [m,n] epilogue).
// ---------------------------------------------------------------------------
#define KC 64
#define NCH 48
#define SPITCH 72                  // bf16 elements per smem row (144 bytes)

__global__ void __launch_bounds__(256)
mma_gemm_kernel(const float* __restrict__ Bq, const float* __restrict__ Bk,
                const float* __restrict__ Bv,
                float* __restrict__ out, int mode)
{
    __shared__ __align__(16) __nv_bfloat16 As[128 * SPITCH];
    __shared__ __align__(16) __nv_bfloat16 Bs[128 * SPITCH];

    const int tid  = threadIdx.x;
    const int wid  = tid >> 5;
    const int lane = tid & 31;
    const int g    = lane >> 2;       // 0..7
    const int t    = lane & 3;        // 0..3
    const int z    = (mode == 0) ? (int)blockIdx.z : 3;
    const int n0   = blockIdx.x * 128;
    const int m0   = blockIdx.y * 128;
    const float* Bi = (mode == 1) ? Bq : (z == 0) ? Bq : (z == 1) ? Bk : Bv;

    const __nv_bfloat16* Ah = (mode == 0) ? (g_xh + (size_t)z * SZX) : g_ch;
    const __nv_bfloat16* Al = (mode == 0) ? (g_xl + (size_t)z * SZX) : g_cl;
    const __nv_bfloat16* Bh = g_wh + (size_t)z * SZW;
    const __nv_bfloat16* Bl = g_wl + (size_t)z * SZW;

    const int warp_m = wid & 3;       // rows 32*warp_m
    const int warp_n = wid >> 2;      // cols 64*warp_n

    float acc[2][8][4];
#pragma unroll
    for (int mi = 0; mi < 2; mi++)
#pragma unroll
        for (int nj = 0; nj < 8; nj++)
#pragma unroll
            for (int e = 0; e < 4; e++) acc[mi][nj][e] = 0.f;

    for (int c = 0; c < NCH; c++) {
        const int term = c >> 4;              // 0: Ah*Bh, 1: Ah*Bl, 2: Al*Bh
        const int kk   = (c & 15) * KC;
        const __nv_bfloat16* aT = (term == 2) ? Al : Ah;
        const __nv_bfloat16* bT = (term == 1) ? Bl : Bh;

        __syncthreads();   // previous chunk's compute done before overwrite

        // Load tiles: 128 rows x 64 bf16 (128B) each = 1024 x 16B segments.
#pragma unroll
        for (int j = 0; j < 4; j++) {
            const int seg = tid * 4 + j;      // 0..1023
            const int r = seg >> 3, o = seg & 7;
            *(uint4*)(As + r * SPITCH + o * 8) =
                *(const uint4*)(aT + (size_t)(m0 + r) * DM + kk + o * 8);
            *(uint4*)(Bs + r * SPITCH + o * 8) =
                *(const uint4*)(bT + (size_t)(n0 + r) * DM + kk + o * 8);
        }
        __syncthreads();

        const uint32_t* A32 = (const uint32_t*)As;   // pitch 36 uint32
        const uint32_t* B32 = (const uint32_t*)Bs;

#pragma unroll
        for (int k16 = 0; k16 < 4; k16++) {
            const int ko2 = k16 * 8;          // uint32 (k-pair) offset

            // A fragments per PTX m16n8k16 spec:
            // a0=(row g, k 2t), a1=(g+8, 2t), a2=(g, 2t+8), a3=(g+8, 2t+8)
            uint32_t a[2][4];
#pragma unroll
            for (int mi = 0; mi < 2; mi++) {
                const int br = warp_m * 32 + mi * 16;
                a[mi][0] = A32[(br + g)     * 36 + ko2 + t];
                a[mi][1] = A32[(br + 8 + g) * 36 + ko2 + t];
                a[mi][2] = A32[(br + g)     * 36 + ko2 + 4 + t];
                a[mi][3] = A32[(br + 8 + g) * 36 + ko2 + 4 + t];
            }
            // B fragments: b0 = B[n=g][k=2t,2t+1], b1 = k+8
            uint32_t b[8][2];
#pragma unroll
            for (int nj = 0; nj < 8; nj++) {
                const int nr = warp_n * 64 + nj * 8 + g;
                b[nj][0] = B32[nr * 36 + ko2 + t];
                b[nj][1] = B32[nr * 36 + ko2 + 4 + t];
            }
#pragma unroll
            for (int mi = 0; mi < 2; mi++)
#pragma unroll
                for (int nj = 0; nj < 8; nj++)
                    MMA16816(acc[mi][nj], a[mi], b[nj]);
        }
    }

    // Epilogue: C fragment: c0,c1=(row g, col 2t,2t+1), c2,c3=(row g+8, same)
    const int nb = n0 + warp_n * 64;
    const int h  = nb >> 6;                    // warp covers exactly one head
#pragma unroll
    for (int mi = 0; mi < 2; mi++) {
        const int rA = m0 + warp_m * 32 + mi * 16 + g;
        const int rB = rA + 8;
#pragma unroll
        for (int nj = 0; nj < 8; nj++) {
            const int col = nj * 8 + t * 2;            // 0..62 within head
            const float b0 = Bi[nb + col], b1 = Bi[nb + col + 1];
            float2 vA = make_float2(acc[mi][nj][0] + b0, acc[mi][nj][1] + b1);
            float2 vB = make_float2(acc[mi][nj][2] + b0, acc[mi][nj][3] + b1);
            if (mode == 0) {
                float* O = (z == 0) ? g_q : (z == 1) ? g_k : g_v;
                const int bbA = rA >> 11, sA = rA & 2047;
                const int bbB = rB >> 11, sB = rB & 2047;
                *(float2*)&O[(((size_t)(bbA * HEADS + h)) * SEQ + sA) * DK + col] = vA;
                *(float2*)&O[(((size_t)(bbB * HEADS + h)) * SEQ + sB) * DK + col] = vB;
            } else {
                *(float2*)&out[(size_t)rA * DM + nb + col] = vA;
                *(float2*)&out[(size_t)rB * DM + nb + col] = vB;
            }
        }
    }
}

// ---------------------------------------------------------------------------
// Flash attention (fp32, online softmax) — unchanged (passing since R1).
// ---------------------------------------------------------------------------
#define ATTN_SMEM_FLOATS (64*65 + 64*65 + 64*68 + 64*68)

__global__ void __launch_bounds__(256)
attn_kernel()
{
    extern __shared__ float sm[];
    float* Qs = sm;
    float* Ks = Qs + 64 * 65;
    float* Vs = Ks + 64 * 65;
    float* Ps = Vs + 64 * 68;

    const int tid = threadIdx.x;
    const int ty = tid >> 4, tx = tid & 15;
    const int r0 = ty * 4, c0 = tx * 4;

    const int bh = blockIdx.y;
    const int q0 = blockIdx.x * 64;
    const float* __restrict__ Qg = g_q + (size_t)bh * SEQ * DK;
    const float* __restrict__ Kg = g_k + (size_t)bh * SEQ * DK;
    const float* __restrict__ Vg = g_v + (size_t)bh * SEQ * DK;

    for (int t = tid; t < 64 * 16; t += 256) {
        const int row = t >> 4;
        const int dq = (t & 15) * 4;
        float4 v = *(const float4*)&Qg[(q0 + row) * DK + dq];
        Qs[(dq + 0) * 65 + row] = v.x * INV_SCALE;
        Qs[(dq + 1) * 65 + row] = v.y * INV_SCALE;
        Qs[(dq + 2) * 65 + row] = v.z * INV_SCALE;
        Qs[(dq + 3) * 65 + row] = v.w * INV_SCALE;
    }

    float m_run[4], l_run[4], o[4][4];
#pragma unroll
    for (int i = 0; i < 4; i++) {
        m_run[i] = -1e30f; l_run[i] = 0.f;
#pragma unroll
        for (int j = 0; j < 4; j++) o[i][j] = 0.f;
    }

    for (int kv0 = 0; kv0 < SEQ; kv0 += 64) {
        __syncthreads();
        for (int t = tid; t < 64 * 16; t += 256) {
            const int row = t >> 4;
            const int dq = (t & 15) * 4;
            float4 kv = *(const float4*)&Kg[(kv0 + row) * DK + dq];
            Ks[(dq + 0) * 65 + row] = kv.x;
            Ks[(dq + 1) * 65 + row] = kv.y;
            Ks[(dq + 2) * 65 + row] = kv.z;
            Ks[(dq + 3) * 65 + row] = kv.w;
            float4 vv = *(const float4*)&Vg[(kv0 + row) * DK + dq];
            *(float4*)&Vs[row * 68 + dq] = vv;
        }
        __syncthreads();

        float s[4][4];
#pragma unroll
        for (int i = 0; i < 4; i++)
#pragma unroll
            for (int j = 0; j < 4; j++) s[i][j] = 0.f;

#pragma unroll 8
        for (int k = 0; k < 64; k++) {
            float a[4], b[4];
#pragma unroll
            for (int i = 0; i < 4; i++) a[i] = Qs[k * 65 + r0 + i];
#pragma unroll
            for (int j = 0; j < 4; j++) b[j] = Ks[k * 65 + c0 + j];
#pragma unroll
            for (int i = 0; i < 4; i++)
#pragma unroll
                for (int j = 0; j < 4; j++) s[i][j] = fmaf(a[i], b[j], s[i][j]);
        }

        float mt[4];
#pragma unroll
        for (int i = 0; i < 4; i++)
            mt[i] = fmaxf(fmaxf(s[i][0], s[i][1]), fmaxf(s[i][2], s[i][3]));
#pragma unroll
        for (int off = 8; off >= 1; off >>= 1) {
#pragma unroll
            for (int i = 0; i < 4; i++)
                mt[i] = fmaxf(mt[i], __shfl_xor_sync(0xffffffffu, mt[i], off));
        }

        float mn[4], corr[4], rs[4];
#pragma unroll
        for (int i = 0; i < 4; i++) {
            mn[i] = fmaxf(m_run[i], mt[i]);
            corr[i] = __expf(m_run[i] - mn[i]);
            rs[i] = 0.f;
        }

#pragma unroll
        for (int i = 0; i < 4; i++) {
            float p0 = __expf(s[i][0] - mn[i]);
            float p1 = __expf(s[i][1] - mn[i]);
            float p2 = __expf(s[i][2] - mn[i]);
            float p3 = __expf(s[i][3] - mn[i]);
            rs[i] = p0 + p1 + p2 + p3;
            *(float4*)&Ps[(r0 + i) * 68 + c0] = make_float4(p0, p1, p2, p3);
        }
#pragma unroll
        for (int off = 8; off >= 1; off >>= 1) {
#pragma unroll
            for (int i = 0; i < 4; i++)
                rs[i] += __shfl_xor_sync(0xffffffffu, rs[i], off);
        }
#pragma unroll
        for (int i = 0; i < 4; i++) {
            l_run[i] = l_run[i] * corr[i] + rs[i];
            m_run[i] = mn[i];
#pragma unroll
            for (int j = 0; j < 4; j++) o[i][j] *= corr[i];
        }
        __syncthreads();

#pragma unroll 8
        for (int j = 0; j < 64; j++) {
            float4 vv = *(const float4*)&Vs[j * 68 + c0];
            float pv[4];
#pragma unroll
            for (int i = 0; i < 4; i++) pv[i] = Ps[(r0 + i) * 68 + j];
#pragma unroll
            for (int i = 0; i < 4; i++) {
                o[i][0] = fmaf(pv[i], vv.x, o[i][0]);
                o[i][1] = fmaf(pv[i], vv.y, o[i][1]);
                o[i][2] = fmaf(pv[i], vv.z, o[i][2]);
                o[i][3] = fmaf(pv[i], vv.w, o[i][3]);
            }
        }
    }

    const int b = bh >> 4;
    const int h = bh & 15;
#pragma unroll
    for (int i = 0; i < 4; i++) {
        const float inv = 1.0f / l_run[i];
        const int row = q0 + r0 + i;
        float* dst = &g_ctx[((size_t)(b * SEQ + row)) * DM + h * DK + c0];
        *(float4*)dst = make_float4(o[i][0] * inv, o[i][1] * inv,
                                    o[i][2] * inv, o[i][3] * inv);
    }
}

// ---------------------------------------------------------------------------
extern "C" void kernel_launch(void* const* d_in, const int* in_sizes, int n_in,
                              void* d_out, int out_size)
{
    const float* query = (const float*)d_in[0];
    const float* key   = (const float*)d_in[1];
    const float* value = (const float*)d_in[2];
    const float* wq = (const float*)d_in[3];
    const float* bq = (const float*)d_in[4];
    const float* wk = (const float*)d_in[5];
    const float* bk = (const float*)d_in[6];
    const float* wv = (const float*)d_in[7];
    const float* bv = (const float*)d_in[8];
    const float* wo = (const float*)d_in[9];
    const float* bo = (const float*)d_in[10];
    float* out = (float*)d_out;

    cudaFuncSetAttribute(attn_kernel, cudaFuncAttributeMaxDynamicSharedMemorySize,
                         ATTN_SMEM_FLOATS * (int)sizeof(float));

    // fp32 -> bf16 hi/lo splits (destinations resolved in device code!)
    cvt_kernel<<<SZX/1024, 256>>>(query, 0, SZX/4);
    cvt_kernel<<<SZX/1024, 256>>>(key,   1, SZX/4);
    cvt_kernel<<<SZX/1024, 256>>>(value, 2, SZX/4);
    cvt_kernel<<<SZW/1024, 256>>>(wq,    3, SZW/4);
    cvt_kernel<<<SZW/1024, 256>>>(wk,    4, SZW/4);
    cvt_kernel<<<SZW/1024, 256>>>(wv,    5, SZW/4);
    cvt_kernel<<<SZW/1024, 256>>>(wo,    6, SZW/4);

    // QKV projections (mma.sync bf16 3-term)
    dim3 gq(DM / 128, MROWS / 128, 3);
    mma_gemm_kernel<<<gq, 256>>>(bq, bk, bv, out, 0);

    // Flash attention (fp32)
    dim3 ga(SEQ / 64, BATCH * HEADS);
    attn_kernel<<<ga, 256, ATTN_SMEM_FLOATS * (int)sizeof(float)>>>();

    // ctx -> bf16 hi/lo (source = g_ctx, resolved in device code), then O proj
    cvt_kernel<<<SZX/1024, 256>>>(nullptr, 7, SZX/4);
    dim3 go(DM / 128, MROWS / 128, 1);
    mma_gemm_kernel<<<go, 256>>>(bo, nullptr, nullptr, out, 1);
}

// round 14
// speedup vs baseline: 1.8743x; 1.5128x over previous
#include <cuda_runtime.h>
#include <cuda_bf16.h>
#include <math.h>
#include <stdint.h>

// Problem constants
#define BATCH 2
#define SEQ   2048
#define DM    1024
#define HEADS 16
#define DK    64
#define MROWS (BATCH*SEQ)   // 4096

#define SZX (MROWS*DM)
#define SZW (DM*DM)
#define SZH (BATCH*HEADS*SEQ*DK)   // 4194304

// ---------------- static device scratch (device-side addressing ONLY) ------
__device__ __align__(256) __nv_bfloat16 g_xh[3*SZX];
__device__ __align__(256) __nv_bfloat16 g_xl[3*SZX];
__device__ __align__(256) __nv_bfloat16 g_wh[4*SZW];
__device__ __align__(256) __nv_bfloat16 g_wl[4*SZW];
__device__ __align__(256) __nv_bfloat16 g_qh[SZH], g_ql[SZH];
__device__ __align__(256) __nv_bfloat16 g_kh[SZH], g_kl[SZH];
__device__ __align__(256) __nv_bfloat16 g_vh[SZH], g_vl[SZH];
__device__ __align__(256) __nv_bfloat16 g_ch[SZX], g_cl[SZX];

// ---------------- mma.sync helper ----------------
#define MMA16816(c, a, b) \
    asm volatile("mma.sync.aligned.m16n8k16.row.col.f32.bf16.bf16.f32 " \
        "{%0,%1,%2,%3}, {%4,%5,%6,%7}, {%8,%9}, {%0,%1,%2,%3};" \
        : "+f"((c)[0]), "+f"((c)[1]), "+f"((c)[2]), "+f"((c)[3]) \
        : "r"((a)[0]), "r"((a)[1]), "r"((a)[2]), "r"((a)[3]), \
          "r"((b)[0]), "r"((b)[1]))

__device__ __forceinline__ uint32_t pk2(float a, float b) {
    __nv_bfloat162 t(__float2bfloat16(a), __float2bfloat16(b));  // a = low
    return *(uint32_t*)&t;
}

// ---------------------------------------------------------------------------
// fp32 -> bf16 hi/lo split (destinations resolved in device code).
// which 0/1/2: g_xh/g_xl slot; 3..6: g_wh/g_wl slot.
// ---------------------------------------------------------------------------
__global__ void __launch_bounds__(256)
cvt_kernel(const float* __restrict__ src, int which, int n4)
{
    int i = blockIdx.x * 256 + threadIdx.x;
    if (i >= n4) return;

    __nv_bfloat16* hi;
    __nv_bfloat16* lo;
    if (which < 3) { hi = g_xh + (size_t)which * SZX;       lo = g_xl + (size_t)which * SZX; }
    else           { hi = g_wh + (size_t)(which - 3) * SZW; lo = g_wl + (size_t)(which - 3) * SZW; }

    float4 v = ((const float4*)src)[i];
    __nv_bfloat16 h0 = __float2bfloat16(v.x);
    __nv_bfloat16 h1 = __float2bfloat16(v.y);
    __nv_bfloat16 h2 = __float2bfloat16(v.z);
    __nv_bfloat16 h3 = __float2bfloat16(v.w);
    __nv_bfloat16 l0 = __float2bfloat16(v.x - __bfloat162float(h0));
    __nv_bfloat16 l1 = __float2bfloat16(v.y - __bfloat162float(h1));
    __nv_bfloat16 l2 = __float2bfloat16(v.z - __bfloat162float(h2));
    __nv_bfloat16 l3 = __float2bfloat16(v.w - __bfloat162float(h3));
    __nv_bfloat162* H = (__nv_bfloat162*)hi;
    __nv_bfloat162* L = (__nv_bfloat162*)lo;
    H[2*i]   = __nv_bfloat162(h0, h1);
    H[2*i+1] = __nv_bfloat162(h2, h3);
    L[2*i]   = __nv_bfloat162(l0, l1);
    L[2*i+1] = __nv_bfloat162(l2, l3);
}

// ---------------------------------------------------------------------------
// mma.sync GEMM (validated R12). mode 0: epilogue -> bf16 hi/lo Q/K/V
// (head-split, Q pre-scaled by 1/8). mode 1: ctx(g_ch/g_cl) @ wo^T -> out fp32.
// ---------------------------------------------------------------------------
#define KC 64
#define NCH 48
#define SPITCH 72                  // bf16 per smem row (144 B)

__global__ void __launch_bounds__(256)
mma_gemm_kernel(const float* __restrict__ Bq, const float* __restrict__ Bk,
                const float* __restrict__ Bv,
                float* __restrict__ out, int mode)
{
    __shared__ __align__(16) __nv_bfloat16 As[128 * SPITCH];
    __shared__ __align__(16) __nv_bfloat16 Bs[128 * SPITCH];

    const int tid  = threadIdx.x;
    const int wid  = tid >> 5;
    const int lane = tid & 31;
    const int g    = lane >> 2;
    const int t    = lane & 3;
    const int z    = (mode == 0) ? (int)blockIdx.z : 3;
    const int n0   = blockIdx.x * 128;
    const int m0   = blockIdx.y * 128;
    const float* Bi = (mode == 1) ? Bq : (z == 0) ? Bq : (z == 1) ? Bk : Bv;

    const __nv_bfloat16* Ah = (mode == 0) ? (g_xh + (size_t)z * SZX) : g_ch;
    const __nv_bfloat16* Al = (mode == 0) ? (g_xl + (size_t)z * SZX) : g_cl;
    const __nv_bfloat16* Bh = g_wh + (size_t)z * SZW;
    const __nv_bfloat16* Bl = g_wl + (size_t)z * SZW;

    const int warp_m = wid & 3;
    const int warp_n = wid >> 2;

    float acc[2][8][4];
#pragma unroll
    for (int mi = 0; mi < 2; mi++)
#pragma unroll
        for (int nj = 0; nj < 8; nj++)
#pragma unroll
            for (int e = 0; e < 4; e++) acc[mi][nj][e] = 0.f;

    for (int c = 0; c < NCH; c++) {
        const int term = c >> 4;
        const int kk   = (c & 15) * KC;
        const __nv_bfloat16* aT = (term == 2) ? Al : Ah;
        const __nv_bfloat16* bT = (term == 1) ? Bl : Bh;

        __syncthreads();
#pragma unroll
        for (int j = 0; j < 4; j++) {
            const int seg = tid * 4 + j;
            const int r = seg >> 3, o = seg & 7;
            *(uint4*)(As + r * SPITCH + o * 8) =
                *(const uint4*)(aT + (size_t)(m0 + r) * DM + kk + o * 8);
            *(uint4*)(Bs + r * SPITCH + o * 8) =
                *(const uint4*)(bT + (size_t)(n0 + r) * DM + kk + o * 8);
        }
        __syncthreads();

        const uint32_t* A32 = (const uint32_t*)As;
        const uint32_t* B32 = (const uint32_t*)Bs;

#pragma unroll
        for (int k16 = 0; k16 < 4; k16++) {
            const int ko2 = k16 * 8;
            uint32_t a[2][4];
#pragma unroll
            for (int mi = 0; mi < 2; mi++) {
                const int br = warp_m * 32 + mi * 16;
                a[mi][0] = A32[(br + g)     * 36 + ko2 + t];
                a[mi][1] = A32[(br + 8 + g) * 36 + ko2 + t];
                a[mi][2] = A32[(br + g)     * 36 + ko2 + 4 + t];
                a[mi][3] = A32[(br + 8 + g) * 36 + ko2 + 4 + t];
            }
            uint32_t b[8][2];
#pragma unroll
            for (int nj = 0; nj < 8; nj++) {
                const int nr = warp_n * 64 + nj * 8 + g;
                b[nj][0] = B32[nr * 36 + ko2 + t];
                b[nj][1] = B32[nr * 36 + ko2 + 4 + t];
            }
#pragma unroll
            for (int mi = 0; mi < 2; mi++)
#pragma unroll
                for (int nj = 0; nj < 8; nj++)
                    MMA16816(acc[mi][nj], a[mi], b[nj]);
        }
    }

    const int nb = n0 + warp_n * 64;
    const int h  = nb >> 6;
#pragma unroll
    for (int mi = 0; mi < 2; mi++) {
        const int rA = m0 + warp_m * 32 + mi * 16 + g;
        const int rB = rA + 8;
#pragma unroll
        for (int nj = 0; nj < 8; nj++) {
            const int col = nj * 8 + t * 2;
            const float b0 = Bi[nb + col], b1 = Bi[nb + col + 1];
            float v0 = acc[mi][nj][0] + b0, v1 = acc[mi][nj][1] + b1;
            float v2 = acc[mi][nj][2] + b0, v3 = acc[mi][nj][3] + b1;
            if (mode == 0) {
                if (z == 0) { v0 *= 0.125f; v1 *= 0.125f; v2 *= 0.125f; v3 *= 0.125f; }
                __nv_bfloat16* H = (z == 0) ? g_qh : (z == 1) ? g_kh : g_vh;
                __nv_bfloat16* L = (z == 0) ? g_ql : (z == 1) ? g_kl : g_vl;
                const int bbA = rA >> 11, sA = rA & 2047;
                const int bbB = rB >> 11, sB = rB & 2047;
                const size_t iA = (((size_t)(bbA * HEADS + h)) * SEQ + sA) * DK + col;
                const size_t iB = (((size_t)(bbB * HEADS + h)) * SEQ + sB) * DK + col;
                float h0 = __bfloat162float(__float2bfloat16(v0));
                float h1 = __bfloat162float(__float2bfloat16(v1));
                float h2 = __bfloat162float(__float2bfloat16(v2));
                float h3 = __bfloat162float(__float2bfloat16(v3));
                *(uint32_t*)&H[iA] = pk2(v0, v1);
                *(uint32_t*)&L[iA] = pk2(v0 - h0, v1 - h1);
                *(uint32_t*)&H[iB] = pk2(v2, v3);
                *(uint32_t*)&L[iB] = pk2(v2 - h2, v3 - h3);
            } else {
                *(float2*)&out[(size_t)rA * DM + nb + col] = make_float2(v0, v1);
                *(float2*)&out[(size_t)rB * DM + nb + col] = make_float2(v2, v3);
            }
        }
    }
}

// ---------------------------------------------------------------------------
// mma.sync flash attention. CTA = (64-row Q tile, bh). 128 threads, 4 warps
// (16-row strips). S = Q K^T 3-term hi/lo; online softmax in C-fragments;
// P hi/lo register repack -> A-fragments; O += P V 3-term with V^T in smem.
// Writes ctx directly as bf16 hi/lo (g_ch/g_cl).
// ---------------------------------------------------------------------------
#define ATILE (64 * SPITCH)                 // bf16 elems per smem tile
#define ATTN_SMEM_BYTES (6 * ATILE * 2)     // Qh Ql Kh Kl Vth Vtl

__global__ void __launch_bounds__(128)
attn_mma_kernel()
{
    extern __shared__ __nv_bfloat16 smb[];
    __nv_bfloat16* Qh  = smb;
    __nv_bfloat16* Ql  = smb + ATILE;
    __nv_bfloat16* Kh  = smb + 2 * ATILE;
    __nv_bfloat16* Kl  = smb + 3 * ATILE;
    __nv_bfloat16* Vth = smb + 4 * ATILE;
    __nv_bfloat16* Vtl = smb + 5 * ATILE;

    const int tid  = threadIdx.x;
    const int wid  = tid >> 5;          // 0..3
    const int lane = tid & 31;
    const int g    = lane >> 2;
    const int t    = lane & 3;
    const int bh   = blockIdx.y;
    const int q0   = blockIdx.x * 64;
    const size_t base = (size_t)bh * SEQ * DK;

    // Load Q tile (hi+lo)
#pragma unroll
    for (int j = 0; j < 4; j++) {
        const int seg = tid * 4 + j;          // 0..511
        const int r = seg >> 3, o = seg & 7;
        *(uint4*)(Qh + r * SPITCH + o * 8) =
            *(const uint4*)(g_qh + base + (size_t)(q0 + r) * DK + o * 8);
        *(uint4*)(Ql + r * SPITCH + o * 8) =
            *(const uint4*)(g_ql + base + (size_t)(q0 + r) * DK + o * 8);
    }
    __syncthreads();

    // Preload Q fragments (A operand), warp strip = rows wid*16..+15
    uint32_t qfh[4][4], qfl[4][4];
    {
        const uint32_t* Q32h = (const uint32_t*)Qh;
        const uint32_t* Q32l = (const uint32_t*)Ql;
        const int br = wid * 16;
#pragma unroll
        for (int kc = 0; kc < 4; kc++) {
            const int ko2 = kc * 8;
            qfh[kc][0] = Q32h[(br + g)     * 36 + ko2 + t];
            qfh[kc][1] = Q32h[(br + 8 + g) * 36 + ko2 + t];
            qfh[kc][2] = Q32h[(br + g)     * 36 + ko2 + 4 + t];
            qfh[kc][3] = Q32h[(br + 8 + g) * 36 + ko2 + 4 + t];
            qfl[kc][0] = Q32l[(br + g)     * 36 + ko2 + t];
            qfl[kc][1] = Q32l[(br + 8 + g) * 36 + ko2 + t];
            qfl[kc][2] = Q32l[(br + g)     * 36 + ko2 + 4 + t];
            qfl[kc][3] = Q32l[(br + 8 + g) * 36 + ko2 + 4 + t];
        }
    }

    float m0 = -1e30f, m1 = -1e30f, l0 = 0.f, l1 = 0.f;
    float o[8][4];
#pragma unroll
    for (int nj = 0; nj < 8; nj++)
#pragma unroll
        for (int e = 0; e < 4; e++) o[nj][e] = 0.f;

    for (int kv0 = 0; kv0 < SEQ; kv0 += 64) {
        __syncthreads();
        // K tiles straight; V tiles transposed into Vt[d][j]
#pragma unroll
        for (int j = 0; j < 4; j++) {
            const int seg = tid * 4 + j;
            const int r = seg >> 3, o8 = seg & 7;
            *(uint4*)(Kh + r * SPITCH + o8 * 8) =
                *(const uint4*)(g_kh + base + (size_t)(kv0 + r) * DK + o8 * 8);
            *(uint4*)(Kl + r * SPITCH + o8 * 8) =
                *(const uint4*)(g_kl + base + (size_t)(kv0 + r) * DK + o8 * 8);
            uint4 vh4 = *(const uint4*)(g_vh + base + (size_t)(kv0 + r) * DK + o8 * 8);
            uint4 vl4 = *(const uint4*)(g_vl + base + (size_t)(kv0 + r) * DK + o8 * 8);
            const __nv_bfloat16* ph = (const __nv_bfloat16*)&vh4;
            const __nv_bfloat16* pl = (const __nv_bfloat16*)&vl4;
#pragma unroll
            for (int i = 0; i < 8; i++) {
                Vth[(o8 * 8 + i) * SPITCH + r] = ph[i];
                Vtl[(o8 * 8 + i) * SPITCH + r] = pl[i];
            }
        }
        __syncthreads();

        const uint32_t* K32h = (const uint32_t*)Kh;
        const uint32_t* K32l = (const uint32_t*)Kl;
        const uint32_t* V32h = (const uint32_t*)Vth;
        const uint32_t* V32l = (const uint32_t*)Vtl;

        // S = Q K^T, 3 terms
        float s[8][4];
#pragma unroll
        for (int nj = 0; nj < 8; nj++)
#pragma unroll
            for (int e = 0; e < 4; e++) s[nj][e] = 0.f;

#pragma unroll
        for (int kc = 0; kc < 4; kc++) {
            const int ko2 = kc * 8;
            uint32_t bh2[8][2], bl2[8][2];
#pragma unroll
            for (int nj = 0; nj < 8; nj++) {
                const int nr = nj * 8 + g;
                bh2[nj][0] = K32h[nr * 36 + ko2 + t];
                bh2[nj][1] = K32h[nr * 36 + ko2 + 4 + t];
                bl2[nj][0] = K32l[nr * 36 + ko2 + t];
                bl2[nj][1] = K32l[nr * 36 + ko2 + 4 + t];
            }
#pragma unroll
            for (int nj = 0; nj < 8; nj++) {
                MMA16816(s[nj], qfh[kc], bh2[nj]);
                MMA16816(s[nj], qfh[kc], bl2[nj]);
                MMA16816(s[nj], qfl[kc], bh2[nj]);
            }
        }

        // Online softmax (rows g / g+8 of this warp's strip)
        float mt0 = -1e30f, mt1 = -1e30f;
#pragma unroll
        for (int nj = 0; nj < 8; nj++) {
            mt0 = fmaxf(mt0, fmaxf(s[nj][0], s[nj][1]));
            mt1 = fmaxf(mt1, fmaxf(s[nj][2], s[nj][3]));
        }
        mt0 = fmaxf(mt0, __shfl_xor_sync(0xffffffffu, mt0, 1));
        mt0 = fmaxf(mt0, __shfl_xor_sync(0xffffffffu, mt0, 2));
        mt1 = fmaxf(mt1, __shfl_xor_sync(0xffffffffu, mt1, 1));
        mt1 = fmaxf(mt1, __shfl_xor_sync(0xffffffffu, mt1, 2));

        const float mn0 = fmaxf(m0, mt0), mn1 = fmaxf(m1, mt1);
        const float cr0 = __expf(m0 - mn0), cr1 = __expf(m1 - mn1);
        float rs0 = 0.f, rs1 = 0.f;
#pragma unroll
        for (int nj = 0; nj < 8; nj++) {
            s[nj][0] = __expf(s[nj][0] - mn0);
            s[nj][1] = __expf(s[nj][1] - mn0);
            s[nj][2] = __expf(s[nj][2] - mn1);
            s[nj][3] = __expf(s[nj][3] - mn1);
            rs0 += s[nj][0] + s[nj][1];
            rs1 += s[nj][2] + s[nj][3];
        }
        rs0 += __shfl_xor_sync(0xffffffffu, rs0, 1);
        rs0 += __shfl_xor_sync(0xffffffffu, rs0, 2);
        rs1 += __shfl_xor_sync(0xffffffffu, rs1, 1);
        rs1 += __shfl_xor_sync(0xffffffffu, rs1, 2);
        l0 = l0 * cr0 + rs0;  l1 = l1 * cr1 + rs1;
        m0 = mn0;  m1 = mn1;
#pragma unroll
        for (int nj = 0; nj < 8; nj++) {
            o[nj][0] *= cr0; o[nj][1] *= cr0;
            o[nj][2] *= cr1; o[nj][3] *= cr1;
        }

        // P fragments (register repack) + O += P V (3 terms)
#pragma unroll
        for (int kc = 0; kc < 4; kc++) {
            const float p00 = s[2*kc][0],   p01 = s[2*kc][1];
            const float p02 = s[2*kc][2],   p03 = s[2*kc][3];
            const float p10 = s[2*kc+1][0], p11 = s[2*kc+1][1];
            const float p12 = s[2*kc+1][2], p13 = s[2*kc+1][3];
            uint32_t aph[4], apl[4];
            aph[0] = pk2(p00, p01);
            aph[1] = pk2(p02, p03);
            aph[2] = pk2(p10, p11);
            aph[3] = pk2(p12, p13);
            apl[0] = pk2(p00 - __bfloat162float(__float2bfloat16(p00)),
                         p01 - __bfloat162float(__float2bfloat16(p01)));
            apl[1] = pk2(p02 - __bfloat162float(__float2bfloat16(p02)),
                         p03 - __bfloat162float(__float2bfloat16(p03)));
            apl[2] = pk2(p10 - __bfloat162float(__float2bfloat16(p10)),
                         p11 - __bfloat162float(__float2bfloat16(p11)));
            apl[3] = pk2(p12 - __bfloat162float(__float2bfloat16(p12)),
                         p13 - __bfloat162float(__float2bfloat16(p13)));
            const int ko2 = kc * 8;
#pragma unroll
            for (int njd = 0; njd < 8; njd++) {
                const int nr = njd * 8 + g;
                uint32_t bvh[2], bvl[2];
                bvh[0] = V32h[nr * 36 + ko2 + t];
                bvh[1] = V32h[nr * 36 + ko2 + 4 + t];
                bvl[0] = V32l[nr * 36 + ko2 + t];
                bvl[1] = V32l[nr * 36 + ko2 + 4 + t];
                MMA16816(o[njd], aph, bvh);
                MMA16816(o[njd], aph, bvl);
                MMA16816(o[njd], apl, bvh);
            }
        }
    }

    // Epilogue: ctx bf16 hi/lo, layout [b*SEQ+s][h*64+d]
    const float inv0 = 1.0f / l0, inv1 = 1.0f / l1;
    const int b = bh >> 4;
    const int h = bh & 15;
    const int rowA = q0 + wid * 16 + g;
    const int rowB = rowA + 8;
#pragma unroll
    for (int njd = 0; njd < 8; njd++) {
        const int col = njd * 8 + t * 2;
        const float v0 = o[njd][0] * inv0, v1 = o[njd][1] * inv0;
        const float v2 = o[njd][2] * inv1, v3 = o[njd][3] * inv1;
        const size_t iA = ((size_t)(b * SEQ + rowA)) * DM + h * 64 + col;
        const size_t iB = ((size_t)(b * SEQ + rowB)) * DM + h * 64 + col;
        const float h0 = __bfloat162float(__float2bfloat16(v0));
        const float h1 = __bfloat162float(__float2bfloat16(v1));
        const float h2 = __bfloat162float(__float2bfloat16(v2));
        const float h3 = __bfloat162float(__float2bfloat16(v3));
        *(uint32_t*)&g_ch[iA] = pk2(v0, v1);
        *(uint32_t*)&g_cl[iA] = pk2(v0 - h0, v1 - h1);
        *(uint32_t*)&g_ch[iB] = pk2(v2, v3);
        *(uint32_t*)&g_cl[iB] = pk2(v2 - h2, v3 - h3);
    }
}

// ---------------------------------------------------------------------------
extern "C" void kernel_launch(void* const* d_in, const int* in_sizes, int n_in,
                              void* d_out, int out_size)
{
    const float* query = (const float*)d_in[0];
    const float* key   = (const float*)d_in[1];
    const float* value = (const float*)d_in[2];
    const float* wq = (const float*)d_in[3];
    const float* bq = (const float*)d_in[4];
    const float* wk = (const float*)d_in[5];
    const float* bk = (const float*)d_in[6];
    const float* wv = (const float*)d_in[7];
    const float* bv = (const float*)d_in[8];
    const float* wo = (const float*)d_in[9];
    const float* bo = (const float*)d_in[10];
    float* out = (float*)d_out;

    cudaFuncSetAttribute(attn_mma_kernel, cudaFuncAttributeMaxDynamicSharedMemorySize,
                         ATTN_SMEM_BYTES);

    // fp32 -> bf16 hi/lo splits
    cvt_kernel<<<SZX/1024, 256>>>(query, 0, SZX/4);
    cvt_kernel<<<SZX/1024, 256>>>(key,   1, SZX/4);
    cvt_kernel<<<SZX/1024, 256>>>(value, 2, SZX/4);
    cvt_kernel<<<SZW/1024, 256>>>(wq,    3, SZW/4);
    cvt_kernel<<<SZW/1024, 256>>>(wk,    4, SZW/4);
    cvt_kernel<<<SZW/1024, 256>>>(wv,    5, SZW/4);
    cvt_kernel<<<SZW/1024, 256>>>(wo,    6, SZW/4);

    // QKV projections -> bf16 hi/lo head-split (Q pre-scaled)
    dim3 gq(DM / 128, MROWS / 128, 3);
    mma_gemm_kernel<<<gq, 256>>>(bq, bk, bv, out, 0);

    // Flash attention on tensor cores -> ctx bf16 hi/lo
    dim3 ga(SEQ / 64, BATCH * HEADS);
    attn_mma_kernel<<<ga, 128, ATTN_SMEM_BYTES>>>();

    // O projection -> out
    dim3 go(DM / 128, MROWS / 128, 1);
    mma_gemm_kernel<<<go, 256>>>(bo, nullptr, nullptr, out, 1);
}

// round 17
// speedup vs baseline: 2.3166x; 1.2360x over previous
#include <cuda_runtime.h>
#include <cuda_bf16.h>
#include <math.h>
#include <stdint.h>

// Problem constants
#define BATCH 2
#define SEQ   2048
#define DM    1024
#define HEADS 16
#define DK    64
#define MROWS (BATCH*SEQ)   // 4096

#define SZX (MROWS*DM)
#define SZW (DM*DM)
#define SZH (BATCH*HEADS*SEQ*DK)

// ---------------- static device scratch (device-side addressing ONLY) ------
__device__ __align__(256) __nv_bfloat16 g_xh[3*SZX];
__device__ __align__(256) __nv_bfloat16 g_xl[3*SZX];
__device__ __align__(256) __nv_bfloat16 g_wh[4*SZW];
__device__ __align__(256) __nv_bfloat16 g_wl[4*SZW];
__device__ __align__(256) __nv_bfloat16 g_qh[SZH], g_ql[SZH];
__device__ __align__(256) __nv_bfloat16 g_kh[SZH], g_kl[SZH];
__device__ __align__(256) __nv_bfloat16 g_vh[SZH], g_vl[SZH];
__device__ __align__(256) __nv_bfloat16 g_ch[SZX], g_cl[SZX];

// ---------------- helpers ----------------
#define MMA16816(c, a, b) \
    asm volatile("mma.sync.aligned.m16n8k16.row.col.f32.bf16.bf16.f32 " \
        "{%0,%1,%2,%3}, {%4,%5,%6,%7}, {%8,%9}, {%0,%1,%2,%3};" \
        : "+f"((c)[0]), "+f"((c)[1]), "+f"((c)[2]), "+f"((c)[3]) \
        : "r"((a)[0]), "r"((a)[1]), "r"((a)[2]), "r"((a)[3]), \
          "r"((b)[0]), "r"((b)[1]))

#define CP_ASYNC16(dst, src) \
    asm volatile("cp.async.cg.shared.global [%0], [%1], 16;" :: "r"(dst), "l"(src) : "memory")
#define CP_COMMIT()   asm volatile("cp.async.commit_group;" ::: "memory")
#define CP_WAIT(n)    asm volatile("cp.async.wait_group %0;" :: "n"(n) : "memory")

__device__ __forceinline__ uint32_t pk2(float a, float b) {
    __nv_bfloat162 t(__float2bfloat16(a), __float2bfloat16(b));  // a = low
    return *(uint32_t*)&t;
}

// ---------------------------------------------------------------------------
// fp32 -> bf16 hi/lo split (destinations resolved in device code).
// ---------------------------------------------------------------------------
__global__ void __launch_bounds__(256)
cvt_kernel(const float* __restrict__ src, int which, int n4)
{
    int i = blockIdx.x * 256 + threadIdx.x;
    if (i >= n4) return;

    __nv_bfloat16* hi;
    __nv_bfloat16* lo;
    if (which < 3) { hi = g_xh + (size_t)which * SZX;       lo = g_xl + (size_t)which * SZX; }
    else           { hi = g_wh + (size_t)(which - 3) * SZW; lo = g_wl + (size_t)(which - 3) * SZW; }

    float4 v = ((const float4*)src)[i];
    __nv_bfloat16 h0 = __float2bfloat16(v.x);
    __nv_bfloat16 h1 = __float2bfloat16(v.y);
    __nv_bfloat16 h2 = __float2bfloat16(v.z);
    __nv_bfloat16 h3 = __float2bfloat16(v.w);
    __nv_bfloat16 l0 = __float2bfloat16(v.x - __bfloat162float(h0));
    __nv_bfloat16 l1 = __float2bfloat16(v.y - __bfloat162float(h1));
    __nv_bfloat16 l2 = __float2bfloat16(v.z - __bfloat162float(h2));
    __nv_bfloat16 l3 = __float2bfloat16(v.w - __bfloat162float(h3));
    __nv_bfloat162* H = (__nv_bfloat162*)hi;
    __nv_bfloat162* L = (__nv_bfloat162*)lo;
    H[2*i]   = __nv_bfloat162(h0, h1);
    H[2*i+1] = __nv_bfloat162(h2, h3);
    L[2*i]   = __nv_bfloat162(l0, l1);
    L[2*i+1] = __nv_bfloat162(l2, l3);
}

// ---------------------------------------------------------------------------
// Pipelined mma.sync GEMM. All 4 tiles (Ah,Al,Bh,Bl) per K-chunk resident;
// 3 hi/lo terms computed per load. cp.async 2-stage.
// mode 0: -> bf16 hi/lo Q/K/V head-split (Q pre-scaled 1/8); mode 1: -> out.
// ---------------------------------------------------------------------------
#define GKC 32
#define GNCH 32                    // 1024 / 32
#define GP 40                      // bf16 pitch (80 B, 16B-aligned rows)
#define GP32 20
#define GT_BYTES (128 * GP * 2)    // 10240
#define GSTAGE (4 * GT_BYTES)      // 40960
#define GEMM_SMEM (2 * GSTAGE)     // 81920

__global__ void __launch_bounds__(256)
mma_gemm_kernel(const float* __restrict__ Bq, const float* __restrict__ Bk,
                const float* __restrict__ Bv,
                float* __restrict__ out, int mode)
{
    extern __shared__ char dsm[];

    const int tid  = threadIdx.x;
    const int wid  = tid >> 5;
    const int lane = tid & 31;
    const int g    = lane >> 2;
    const int t    = lane & 3;
    const int z    = (mode == 0) ? (int)blockIdx.z : 3;
    const int n0   = blockIdx.x * 128;
    const int m0   = blockIdx.y * 128;
    const float* Bi = (mode == 1) ? Bq : (z == 0) ? Bq : (z == 1) ? Bk : Bv;

    const __nv_bfloat16* Ah = (mode == 0) ? (g_xh + (size_t)z * SZX) : g_ch;
    const __nv_bfloat16* Al = (mode == 0) ? (g_xl + (size_t)z * SZX) : g_cl;
    const __nv_bfloat16* Bh = g_wh + (size_t)z * SZW;
    const __nv_bfloat16* Bl = g_wl + (size_t)z * SZW;

    const uint32_t sb = (uint32_t)__cvta_generic_to_shared(dsm);
    const int warp_m = wid & 3;
    const int warp_n = wid >> 2;

    float acc[2][8][4];
#pragma unroll
    for (int mi = 0; mi < 2; mi++)
#pragma unroll
        for (int nj = 0; nj < 8; nj++)
#pragma unroll
            for (int e = 0; e < 4; e++) acc[mi][nj][e] = 0.f;

    auto prefetch = [&](int c) {
        const int kk = c * GKC;
        const uint32_t stg = sb + (c & 1) * GSTAGE;
#pragma unroll
        for (int it = 0; it < 8; it++) {
            const int e = tid + it * 256;      // 0..2047
            const int tile = e >> 9;
            const int w = e & 511;
            const int r = w >> 2, o = w & 3;
            const __nv_bfloat16* src =
                (tile == 0) ? (Ah + (size_t)(m0 + r) * DM + kk + o * 8) :
                (tile == 1) ? (Al + (size_t)(m0 + r) * DM + kk + o * 8) :
                (tile == 2) ? (Bh + (size_t)(n0 + r) * DM + kk + o * 8) :
                              (Bl + (size_t)(n0 + r) * DM + kk + o * 8);
            CP_ASYNC16(stg + tile * GT_BYTES + r * 80 + o * 16, src);
        }
        CP_COMMIT();
    };

    prefetch(0);
    prefetch(1);

    for (int c = 0; c < GNCH; c++) {
        if (c < GNCH - 2) { CP_WAIT(1); } else { CP_WAIT(0); }
        __syncthreads();

        const char* stg = dsm + (c & 1) * GSTAGE;
        const uint32_t* A32h = (const uint32_t*)(stg);
        const uint32_t* A32l = (const uint32_t*)(stg + GT_BYTES);
        const uint32_t* B32h = (const uint32_t*)(stg + 2 * GT_BYTES);
        const uint32_t* B32l = (const uint32_t*)(stg + 3 * GT_BYTES);

#pragma unroll
        for (int k16 = 0; k16 < 2; k16++) {
            const int ko2 = k16 * 8;
            uint32_t ahf[2][4], alf[2][4];
#pragma unroll
            for (int mi = 0; mi < 2; mi++) {
                const int br = warp_m * 32 + mi * 16;
                ahf[mi][0] = A32h[(br + g)     * GP32 + ko2 + t];
                ahf[mi][1] = A32h[(br + 8 + g) * GP32 + ko2 + t];
                ahf[mi][2] = A32h[(br + g)     * GP32 + ko2 + 4 + t];
                ahf[mi][3] = A32h[(br + 8 + g) * GP32 + ko2 + 4 + t];
                alf[mi][0] = A32l[(br + g)     * GP32 + ko2 + t];
                alf[mi][1] = A32l[(br + 8 + g) * GP32 + ko2 + t];
                alf[mi][2] = A32l[(br + g)     * GP32 + ko2 + 4 + t];
                alf[mi][3] = A32l[(br + 8 + g) * GP32 + ko2 + 4 + t];
            }
            uint32_t bhf[8][2], blf[8][2];
#pragma unroll
            for (int nj = 0; nj < 8; nj++) {
                const int nr = warp_n * 64 + nj * 8 + g;
                bhf[nj][0] = B32h[nr * GP32 + ko2 + t];
                bhf[nj][1] = B32h[nr * GP32 + ko2 + 4 + t];
                blf[nj][0] = B32l[nr * GP32 + ko2 + t];
                blf[nj][1] = B32l[nr * GP32 + ko2 + 4 + t];
            }
#pragma unroll
            for (int mi = 0; mi < 2; mi++)
#pragma unroll
                for (int nj = 0; nj < 8; nj++) {
                    MMA16816(acc[mi][nj], ahf[mi], bhf[nj]);
                    MMA16816(acc[mi][nj], ahf[mi], blf[nj]);
                    MMA16816(acc[mi][nj], alf[mi], bhf[nj]);
                }
        }
        __syncthreads();
        if (c + 2 < GNCH) prefetch(c + 2);
    }

    // Epilogue (layout identical to R14)
    const int nb = n0 + warp_n * 64;
    const int h  = nb >> 6;
#pragma unroll
    for (int mi = 0; mi < 2; mi++) {
        const int rA = m0 + warp_m * 32 + mi * 16 + g;
        const int rB = rA + 8;
#pragma unroll
        for (int nj = 0; nj < 8; nj++) {
            const int col = nj * 8 + t * 2;
            const float b0 = Bi[nb + col], b1 = Bi[nb + col + 1];
            float v0 = acc[mi][nj][0] + b0, v1 = acc[mi][nj][1] + b1;
            float v2 = acc[mi][nj][2] + b0, v3 = acc[mi][nj][3] + b1;
            if (mode == 0) {
                if (z == 0) { v0 *= 0.125f; v1 *= 0.125f; v2 *= 0.125f; v3 *= 0.125f; }
                __nv_bfloat16* H = (z == 0) ? g_qh : (z == 1) ? g_kh : g_vh;
                __nv_bfloat16* L = (z == 0) ? g_ql : (z == 1) ? g_kl : g_vl;
                const int bbA = rA >> 11, sA = rA & 2047;
                const int bbB = rB >> 11, sB = rB & 2047;
                const size_t iA = (((size_t)(bbA * HEADS + h)) * SEQ + sA) * DK + col;
                const size_t iB = (((size_t)(bbB * HEADS + h)) * SEQ + sB) * DK + col;
                float h0 = __bfloat162float(__float2bfloat16(v0));
                float h1 = __bfloat162float(__float2bfloat16(v1));
                float h2 = __bfloat162float(__float2bfloat16(v2));
                float h3 = __bfloat162float(__float2bfloat16(v3));
                *(uint32_t*)&H[iA] = pk2(v0, v1);
                *(uint32_t*)&L[iA] = pk2(v0 - h0, v1 - h1);
                *(uint32_t*)&H[iB] = pk2(v2, v3);
                *(uint32_t*)&L[iB] = pk2(v2 - h2, v3 - h3);
            } else {
                *(float2*)&out[(size_t)rA * DM + nb + col] = make_float2(v0, v1);
                *(float2*)&out[(size_t)rB * DM + nb + col] = make_float2(v2, v3);
            }
        }
    }
}

// ---------------------------------------------------------------------------
// Pipelined mma.sync flash attention. cp.async 2-stage for Kh/Kl/Vh/Vl.
// V stays row-major; PV B-fragments read via paired LDS.U16 (no transpose).
// ---------------------------------------------------------------------------
#define AP 72
#define AP32 36
#define AT_B (64 * AP * 2)          // 9216
#define ASTAGE (4 * AT_B)           // 36864
#define AQ_B (2 * AT_B)             // Qh + Ql
#define ATTN_SMEM (AQ_B + 2 * ASTAGE)   // 92160

__global__ void __launch_bounds__(128)
attn_mma_kernel()
{
    extern __shared__ char asm_[];
    __nv_bfloat16* Qh = (__nv_bfloat16*)asm_;
    __nv_bfloat16* Ql = (__nv_bfloat16*)(asm_ + AT_B);

    const int tid  = threadIdx.x;
    const int wid  = tid >> 5;
    const int lane = tid & 31;
    const int g    = lane >> 2;
    const int t    = lane & 3;
    const int bh   = blockIdx.y;
    const int q0   = blockIdx.x * 64;
    const size_t base = (size_t)bh * SEQ * DK;
    const uint32_t sb = (uint32_t)__cvta_generic_to_shared(asm_);

    auto prefetch = [&](int c) {
        const int kv0 = c * 64;
        const uint32_t stg = sb + AQ_B + (c & 1) * ASTAGE;
#pragma unroll
        for (int it = 0; it < 16; it++) {
            const int e = tid + it * 128;     // 0..2047
            const int tile = e >> 9;
            const int w = e & 511;
            const int r = w >> 3, o = w & 7;
            const __nv_bfloat16* src =
                (tile == 0) ? (g_kh + base + (size_t)(kv0 + r) * DK + o * 8) :
                (tile == 1) ? (g_kl + base + (size_t)(kv0 + r) * DK + o * 8) :
                (tile == 2) ? (g_vh + base + (size_t)(kv0 + r) * DK + o * 8) :
                              (g_vl + base + (size_t)(kv0 + r) * DK + o * 8);
            CP_ASYNC16(stg + tile * AT_B + r * 144 + o * 16, src);
        }
        CP_COMMIT();
    };

    // Q tile (sync load) + start K/V pipeline
#pragma unroll
    for (int j = 0; j < 4; j++) {
        const int seg = tid * 4 + j;          // 0..511
        const int r = seg >> 3, o = seg & 7;
        *(uint4*)(Qh + r * AP + o * 8) =
            *(const uint4*)(g_qh + base + (size_t)(q0 + r) * DK + o * 8);
        *(uint4*)(Ql + r * AP + o * 8) =
            *(const uint4*)(g_ql + base + (size_t)(q0 + r) * DK + o * 8);
    }
    prefetch(0);
    prefetch(1);
    __syncthreads();

    // Preload Q fragments
    uint32_t qfh[4][4], qfl[4][4];
    {
        const uint32_t* Q32h = (const uint32_t*)Qh;
        const uint32_t* Q32l = (const uint32_t*)Ql;
        const int br = wid * 16;
#pragma unroll
        for (int kc = 0; kc < 4; kc++) {
            const int ko2 = kc * 8;
            qfh[kc][0] = Q32h[(br + g)     * AP32 + ko2 + t];
            qfh[kc][1] = Q32h[(br + 8 + g) * AP32 + ko2 + t];
            qfh[kc][2] = Q32h[(br + g)     * AP32 + ko2 + 4 + t];
            qfh[kc][3] = Q32h[(br + 8 + g) * AP32 + ko2 + 4 + t];
            qfl[kc][0] = Q32l[(br + g)     * AP32 + ko2 + t];
            qfl[kc][1] = Q32l[(br + 8 + g) * AP32 + ko2 + t];
            qfl[kc][2] = Q32l[(br + g)     * AP32 + ko2 + 4 + t];
            qfl[kc][3] = Q32l[(br + 8 + g) * AP32 + ko2 + 4 + t];
        }
    }

    float m0 = -1e30f, m1 = -1e30f, l0 = 0.f, l1 = 0.f;
    float o[8][4];
#pragma unroll
    for (int nj = 0; nj < 8; nj++)
#pragma unroll
        for (int e = 0; e < 4; e++) o[nj][e] = 0.f;

    const int NT = SEQ / 64;   // 32
    for (int c = 0; c < NT; c++) {
        if (c < NT - 2) { CP_WAIT(1); } else { CP_WAIT(0); }
        __syncthreads();

        const char* stg = asm_ + AQ_B + (c & 1) * ASTAGE;
        const uint32_t* K32h = (const uint32_t*)(stg);
        const uint32_t* K32l = (const uint32_t*)(stg + AT_B);
        const uint16_t* V16h = (const uint16_t*)(stg + 2 * AT_B);
        const uint16_t* V16l = (const uint16_t*)(stg + 3 * AT_B);

        // S = Q K^T, 3 terms
        float s[8][4];
#pragma unroll
        for (int nj = 0; nj < 8; nj++)
#pragma unroll
            for (int e = 0; e < 4; e++) s[nj][e] = 0.f;

#pragma unroll
        for (int kc = 0; kc < 4; kc++) {
            const int ko2 = kc * 8;
            uint32_t bh2[8][2], bl2[8][2];
#pragma unroll
            for (int nj = 0; nj < 8; nj++) {
                const int nr = nj * 8 + g;
                bh2[nj][0] = K32h[nr * AP32 + ko2 + t];
                bh2[nj][1] = K32h[nr * AP32 + ko2 + 4 + t];
                bl2[nj][0] = K32l[nr * AP32 + ko2 + t];
                bl2[nj][1] = K32l[nr * AP32 + ko2 + 4 + t];
            }
#pragma unroll
            for (int nj = 0; nj < 8; nj++) {
                MMA16816(s[nj], qfh[kc], bh2[nj]);
                MMA16816(s[nj], qfh[kc], bl2[nj]);
                MMA16816(s[nj], qfl[kc], bh2[nj]);
            }
        }

        // Online softmax
        float mt0 = -1e30f, mt1 = -1e30f;
#pragma unroll
        for (int nj = 0; nj < 8; nj++) {
            mt0 = fmaxf(mt0, fmaxf(s[nj][0], s[nj][1]));
            mt1 = fmaxf(mt1, fmaxf(s[nj][2], s[nj][3]));
        }
        mt0 = fmaxf(mt0, __shfl_xor_sync(0xffffffffu, mt0, 1));
        mt0 = fmaxf(mt0, __shfl_xor_sync(0xffffffffu, mt0, 2));
        mt1 = fmaxf(mt1, __shfl_xor_sync(0xffffffffu, mt1, 1));
        mt1 = fmaxf(mt1, __shfl_xor_sync(0xffffffffu, mt1, 2));

        const float mn0 = fmaxf(m0, mt0), mn1 = fmaxf(m1, mt1);
        const float cr0 = __expf(m0 - mn0), cr1 = __expf(m1 - mn1);
        float rs0 = 0.f, rs1 = 0.f;
#pragma unroll
        for (int nj = 0; nj < 8; nj++) {
            s[nj][0] = __expf(s[nj][0] - mn0);
            s[nj][1] = __expf(s[nj][1] - mn0);
            s[nj][2] = __expf(s[nj][2] - mn1);
            s[nj][3] = __expf(s[nj][3] - mn1);
            rs0 += s[nj][0] + s[nj][1];
            rs1 += s[nj][2] + s[nj][3];
        }
        rs0 += __shfl_xor_sync(0xffffffffu, rs0, 1);
        rs0 += __shfl_xor_sync(0xffffffffu, rs0, 2);
        rs1 += __shfl_xor_sync(0xffffffffu, rs1, 1);
        rs1 += __shfl_xor_sync(0xffffffffu, rs1, 2);
        l0 = l0 * cr0 + rs0;  l1 = l1 * cr1 + rs1;
        m0 = mn0;  m1 = mn1;
#pragma unroll
        for (int nj = 0; nj < 8; nj++) {
            o[nj][0] *= cr0; o[nj][1] *= cr0;
            o[nj][2] *= cr1; o[nj][3] *= cr1;
        }

        // P fragments + O += P V (V row-major, paired U16 reads)
#pragma unroll
        for (int kc = 0; kc < 4; kc++) {
            const float p00 = s[2*kc][0],   p01 = s[2*kc][1];
            const float p02 = s[2*kc][2],   p03 = s[2*kc][3];
            const float p10 = s[2*kc+1][0], p11 = s[2*kc+1][1];
            const float p12 = s[2*kc+1][2], p13 = s[2*kc+1][3];
            uint32_t aph[4], apl[4];
            aph[0] = pk2(p00, p01);
            aph[1] = pk2(p02, p03);
            aph[2] = pk2(p10, p11);
            aph[3] = pk2(p12, p13);
            apl[0] = pk2(p00 - __bfloat162float(__float2bfloat16(p00)),
                         p01 - __bfloat162float(__float2bfloat16(p01)));
            apl[1] = pk2(p02 - __bfloat162float(__float2bfloat16(p02)),
                         p03 - __bfloat162float(__float2bfloat16(p03)));
            apl[2] = pk2(p10 - __bfloat162float(__float2bfloat16(p10)),
                         p11 - __bfloat162float(__float2bfloat16(p11)));
            apl[3] = pk2(p12 - __bfloat162float(__float2bfloat16(p12)),
                         p13 - __bfloat162float(__float2bfloat16(p13)));

            const int j0 = kc * 16 + 2 * t;
            const int r0o = j0 * AP, r1o = (j0 + 1) * AP;
            const int r8o = (j0 + 8) * AP, r9o = (j0 + 9) * AP;
#pragma unroll
            for (int njd = 0; njd < 8; njd++) {
                const int nr = njd * 8 + g;
                uint32_t bvh[2], bvl[2];
                bvh[0] = (uint32_t)V16h[r0o + nr] | ((uint32_t)V16h[r1o + nr] << 16);
                bvh[1] = (uint32_t)V16h[r8o + nr] | ((uint32_t)V16h[r9o + nr] << 16);
                bvl[0] = (uint32_t)V16l[r0o + nr] | ((uint32_t)V16l[r1o + nr] << 16);
                bvl[1] = (uint32_t)V16l[r8o + nr] | ((uint32_t)V16l[r9o + nr] << 16);
                MMA16816(o[njd], aph, bvh);
                MMA16816(o[njd], aph, bvl);
                MMA16816(o[njd], apl, bvh);
            }
        }
        __syncthreads();
        if (c + 2 < NT) prefetch(c + 2);
    }

    // Epilogue: ctx bf16 hi/lo, layout [b*SEQ+s][h*64+d]
    const float inv0 = 1.0f / l0, inv1 = 1.0f / l1;
    const int b = bh >> 4;
    const int h = bh & 15;
    const int rowA = q0 + wid * 16 + g;
    const int rowB = rowA + 8;
#pragma unroll
    for (int njd = 0; njd < 8; njd++) {
        const int col = njd * 8 + t * 2;
        const float v0 = o[njd][0] * inv0, v1 = o[njd][1] * inv0;
        const float v2 = o[njd][2] * inv1, v3 = o[njd][3] * inv1;
        const size_t iA = ((size_t)(b * SEQ + rowA)) * DM + h * 64 + col;
        const size_t iB = ((size_t)(b * SEQ + rowB)) * DM + h * 64 + col;
        const float h0 = __bfloat162float(__float2bfloat16(v0));
        const float h1 = __bfloat162float(__float2bfloat16(v1));
        const float h2 = __bfloat162float(__float2bfloat16(v2));
        const float h3 = __bfloat162float(__float2bfloat16(v3));
        *(uint32_t*)&g_ch[iA] = pk2(v0, v1);
        *(uint32_t*)&g_cl[iA] = pk2(v0 - h0, v1 - h1);
        *(uint32_t*)&g_ch[iB] = pk2(v2, v3);
        *(uint32_t*)&g_cl[iB] = pk2(v2 - h2, v3 - h3);
    }
}

// ---------------------------------------------------------------------------
extern "C" void kernel_launch(void* const* d_in, const int* in_sizes, int n_in,
                              void* d_out, int out_size)
{
    const float* query = (const float*)d_in[0];
    const float* key   = (const float*)d_in[1];
    const float* value = (const float*)d_in[2];
    const float* wq = (const float*)d_in[3];
    const float* bq = (const float*)d_in[4];
    const float* wk = (const float*)d_in[5];
    const float* bk = (const float*)d_in[6];
    const float* wv = (const float*)d_in[7];
    const float* bv = (const float*)d_in[8];
    const float* wo = (const float*)d_in[9];
    const float* bo = (const float*)d_in[10];
    float* out = (float*)d_out;

    cudaFuncSetAttribute(mma_gemm_kernel, cudaFuncAttributeMaxDynamicSharedMemorySize,
                         GEMM_SMEM);
    cudaFuncSetAttribute(attn_mma_kernel, cudaFuncAttributeMaxDynamicSharedMemorySize,
                         ATTN_SMEM);

    // fp32 -> bf16 hi/lo splits
    cvt_kernel<<<SZX/1024, 256>>>(query, 0, SZX/4);
    cvt_kernel<<<SZX/1024, 256>>>(key,   1, SZX/4);
    cvt_kernel<<<SZX/1024, 256>>>(value, 2, SZX/4);
    cvt_kernel<<<SZW/1024, 256>>>(wq,    3, SZW/4);
    cvt_kernel<<<SZW/1024, 256>>>(wk,    4, SZW/4);
    cvt_kernel<<<SZW/1024, 256>>>(wv,    5, SZW/4);
    cvt_kernel<<<SZW/1024, 256>>>(wo,    6, SZW/4);

    // QKV projections -> bf16 hi/lo head-split (Q pre-scaled)
    dim3 gq(DM / 128, MROWS / 128, 3);
    mma_gemm_kernel<<<gq, 256, GEMM_SMEM>>>(bq, bk, bv, out, 0);

    // Flash attention on tensor cores -> ctx bf16 hi/lo
    dim3 ga(SEQ / 64, BATCH * HEADS);
    attn_mma_kernel<<<ga, 128, ATTN_SMEM>>>();

    // O projection -> out
    dim3 go(DM / 128, MROWS / 128, 1);
    mma_gemm_kernel<<<go, 256, GEMM_SMEM>>>(bo, nullptr, nullptr, out, 1);
}